// round 16
// baseline (speedup 1.0000x reference)
#include <cuda_runtime.h>
#include <math.h>
#include <stdint.h>

// RVQE: 12-qubit real statevector recurrent cell, B=64, T=9 (8 scan steps).
// One CTA per batch element; state = 4096 floats = 256 threads x 8 packed f32x2.
// Global amplitude index g12 (12 bits), g12 = (t << 4) | r:
//   r bits: bit0=lane11(anc1), bit1=lane10(anc0), bit2=lane9(PACKED), bit3=lane8
//   t bits 0..4 (warp lane): lanes 7,6,5,4,3  -> __shfl_xor (mask 1<<(7-lane))
//   t bits 5,6,7: lanes 2,1,0 -> smem exchange
// PACKING: P[j], j = a*4 + i, i = (anc0<<1)|anc1, a = lane8 bit.
//   P[j].lo = lane9=0, P[j].hi = lane9=1.
//
// Fused neuron algebra (validated rounds 3/5/8): per stage
//   chain = E(a_0) C_0 G_0 T'(D1) C_1 G_1 ... T'(D9) C_9 G_9 F(a_9)
// NEW (this round): adjacent fusion TG_n = T'(D_n) o G_{n-1} and FG = F o G_9.
// Chain per stage shrinks from 31 dependent gate stages to 21:
//   E C0 TG1 C1 TG2 C2 ... TG9 C9 FG
// TG rows (per a-group), with C,S from the step-invariant table and
// cg,sg of gate n-1 (se = +/-sg by the outlane bit):
//   y0 =  C x0 + Sse x1 + Scg x3
//   y1 =  Ccg x1 - S x2 - Cse x3
//   y2 =  Scg x1 + C x2 - Sse x3
//   y3 = -S x0 + Cse x1 + Ccg x3
// FG rows: y0 = C x0 - Sse x1 - Scg x3 ; y1 = Ccg x1 + S x2 - Cse x3
//          y2 = -S x0 - Cse x1 - Ccg x3 ; y3 = -Scg x1 + C x2 + Sse x3
//
// SPARSITY EXPLOIT (validated round 14): steps start from compressed phi;
// P = sigma_t * invn * phi[chunk] replaces stage-0 lane0..5 RYs + projection.

namespace {

typedef unsigned long long u64;

constexpr int NTH   = 256;
constexpr int TT    = 9;
constexpr int NSTEP = 8;
constexpr int NIDX  = 22;   // 18 deltas + 2 entries + 2 trailings
constexpr int STq   = 9;    // exch stride in u64 (8 + 1 pad; odd -> conflict-free)
constexpr int CSW   = 73;   // coef table per-thread stride in u64 (72 + 1 pad)
constexpr u64 SGN2  = 0x8000000080000000ULL;

// dynamic smem layout (u64 units)
constexpr int OFF_A   = 0;
constexpr int OFF_B   = NTH * STq;         // 2304
constexpr int OFF_TAB = OFF_B + NTH * STq; // 4608
constexpr int DYN_U64 = OFF_TAB + NTH * CSW; // 23296 u64 = 186368 B

__device__ __forceinline__ u64 pk(float lo, float hi) {
    u64 r; asm("mov.b64 %0,{%1,%2};" : "=l"(r) : "f"(lo), "f"(hi)); return r;
}
__device__ __forceinline__ void upk(u64 u, float& lo, float& hi) {
    asm("mov.b64 {%0,%1},%2;" : "=f"(lo), "=f"(hi) : "l"(u));
}
__device__ __forceinline__ u64 bc(float x) { return pk(x, x); }
__device__ __forceinline__ u64 f2mul(u64 a, u64 b) {
    u64 d; asm("mul.rn.f32x2 %0,%1,%2;" : "=l"(d) : "l"(a), "l"(b)); return d;
}
__device__ __forceinline__ u64 f2fma(u64 a, u64 b, u64 c) {
    u64 d; asm("fma.rn.f32x2 %0,%1,%2,%3;" : "=l"(d) : "l"(a), "l"(b), "l"(c)); return d;
}
__device__ __forceinline__ u64 f2neg(u64 a) { return a ^ SGN2; }
__device__ __forceinline__ u64 f2swap(u64 a) { float lo, hi; upk(a, lo, hi); return pk(hi, lo); }

// ---- stage RY pieces ----

__device__ __forceinline__ void ry_lane9(u64* P, u64 C, u64 SW) {
#pragma unroll
    for (int j = 0; j < 8; j++)
        P[j] = f2fma(SW, f2swap(P[j]), f2mul(C, P[j]));
}

__device__ __forceinline__ void ry_lane8(u64* P, float c, float s) {
    u64 C = bc(c), S = bc(s), NS = bc(-s);
#pragma unroll
    for (int i = 0; i < 4; i++) {
        u64 u = P[i], w = P[4 + i];
        P[i]     = f2fma(NS, w, f2mul(C, u));
        P[4 + i] = f2fma(S,  u, f2mul(C, w));
    }
}

__device__ __forceinline__ void ry_shfl(u64* P, int t, int m, float c, float s) {
    u64 C = bc(c), SE = bc((t & m) ? s : -s);
#pragma unroll
    for (int j = 0; j < 8; j++) {
        u64 w = __shfl_xor_sync(0xffffffffu, P[j], m);
        P[j] = f2fma(SE, w, f2mul(C, P[j]));
    }
}

// Combined RY(lane0)*RY(lane1) (t bits 7,6): one sync, 4-way gather.
__device__ __forceinline__ void ry_smem4(u64* P, int t,
                                         float c0, float s0, float c1, float s1,
                                         u64* X) {
#pragma unroll
    for (int j = 0; j < 8; j++) X[t * STq + j] = P[j];
    __syncthreads();
    int a  = (t >> 7) & 1;
    int bb = (t >> 6) & 1;
    float r0a0 = a  ? s0 : c0;
    float r0a1 = a  ? c0 : -s0;
    float r1b0 = bb ? s1 : c1;
    float r1b1 = bb ? c1 : -s1;
    u64 k00 = bc(r0a0 * r1b0), k01 = bc(r0a0 * r1b1);
    u64 k10 = bc(r0a1 * r1b0), k11 = bc(r0a1 * r1b1);
    int base = t & 63;
    const u64* x00 = X + base * STq;
    const u64* x01 = X + (base | 64)  * STq;
    const u64* x10 = X + (base | 128) * STq;
    const u64* x11 = X + (base | 192) * STq;
#pragma unroll
    for (int j = 0; j < 8; j++)
        P[j] = f2fma(k00, x00[j],
               f2fma(k01, x01[j],
               f2fma(k10, x10[j], f2mul(k11, x11[j]))));
    // no trailing sync: ping-pong ordering
}

// RY on lane2 (t bit5): 2-way exchange, one sync.
__device__ __forceinline__ void ry_smem1(u64* P, int t, float c, float s, u64* X) {
#pragma unroll
    for (int j = 0; j < 8; j++) X[t * STq + j] = P[j];
    __syncthreads();
    const u64* xp = X + (t ^ 32) * STq;
    u64 C = bc(c), SE = bc((t & 32) ? s : -s);
#pragma unroll
    for (int j = 0; j < 8; j++) P[j] = f2fma(SE, xp[j], f2mul(C, P[j]));
    // no trailing sync: ping-pong ordering
}

// ---- CiY pieces (ctrl anc1: odd j) ----

__device__ __forceinline__ void ciy_lane9(u64* P) {
#pragma unroll
    for (int j = 1; j < 8; j += 2) {
        float lo, hi; upk(P[j], lo, hi);
        P[j] = pk(hi, -lo);
    }
}

__device__ __forceinline__ void ciy_lane8(u64* P) {
#pragma unroll
    for (int i = 1; i < 4; i += 2) {
        u64 p0 = P[i];
        P[i] = P[4 + i];
        P[4 + i] = f2neg(p0);
    }
}

__device__ __forceinline__ void ciy_shfl(u64* P, int t, int m) {
    u64 sgn = (t & m) ? SGN2 : 0ULL;
#pragma unroll
    for (int j = 1; j < 8; j += 2) {
        u64 w = __shfl_xor_sync(0xffffffffu, P[j], m);
        P[j] = w ^ sgn;
    }
}

// Cross-warp CiY: one sync, ping-pong buffer.
__device__ __forceinline__ void ciy_smem(u64* P, int t, int m, u64* X) {
#pragma unroll
    for (int j = 1; j < 8; j += 2) X[t * STq + (j >> 1)] = P[j];
    __syncthreads();
    const u64* p = X + (t ^ m) * STq;
    u64 sgn = (t & m) ? SGN2 : 0ULL;
#pragma unroll
    for (int j = 1; j < 8; j += 2) P[j] = p[j >> 1] ^ sgn;
    // no trailing sync: ping-pong ordering
}

// ---- fused neuron ops (packed over lane9; loop over a = lane8 bit) ----
// x_i = P[a*4+i]: x0=(0,0) x1=(0,1) x2=(1,0) x3=(1,1) of (anc0,anc1)

// TG_n = T'(C,S from table) o G(cg, se).  se = -sg when neg flag set, else +sg.
__device__ __forceinline__ void applyTG(u64* P, const u64* cs, u64 CG, u64 SG,
                                        bool neg0, bool neg1) {
#pragma unroll
    for (int a = 0; a < 2; a++) {
        u64 C  = cs[a * 2 + 0];
        u64 S  = cs[a * 2 + 1];
        u64 D  = f2mul(S, CG);                 // S*cg
        u64 E2 = f2mul(C, CG);                 // C*cg
        u64 Bp = f2mul(S, SG);                 // S*sg
        u64 Fp = f2mul(C, SG);                 // C*sg
        bool ng = a ? neg1 : neg0;
        u64 B  = ng ? f2neg(Bp) : Bp;          // S*se
        u64 F2 = ng ? f2neg(Fp) : Fp;          // C*se
        u64 NS = f2neg(S);
        u64 x0 = P[4*a+0], x1 = P[4*a+1], x2 = P[4*a+2], x3 = P[4*a+3];
        P[4*a+0] = f2fma(C,  x0, f2fma(B,         x1, f2mul(D,         x3)));
        P[4*a+1] = f2fma(E2, x1, f2fma(NS,        x2, f2mul(f2neg(F2), x3)));
        P[4*a+2] = f2fma(D,  x1, f2fma(C,         x2, f2mul(f2neg(B),  x3)));
        P[4*a+3] = f2fma(NS, x0, f2fma(F2,        x1, f2mul(E2,        x3)));
    }
}

__device__ __forceinline__ void applyE(u64* P, float cb, float sb,
                                       const u64* DC, const u64* DS) {
    u64 CB = bc(cb), SB = bc(sb), NSB = bc(-sb);
#pragma unroll
    for (int a = 0; a < 2; a++) {
        u64 C  = f2fma(NSB, DS[a], f2mul(CB, DC[a]));
        u64 S  = f2fma(SB,  DC[a], f2mul(CB, DS[a]));
        u64 NS = f2neg(S);
        u64 x0 = P[4*a+0], x1 = P[4*a+1], x2 = P[4*a+2], x3 = P[4*a+3];
        P[4*a+0] = f2fma(NS, x2, f2mul(C, x0));
        P[4*a+1] = f2fma(NS, x3, f2mul(C, x1));
        P[4*a+2] = f2fma(S,  x1, f2mul(C, x3));
        P[4*a+3] = f2neg(f2fma(S, x0, f2mul(C, x2)));
    }
}

// FG = F(a_9) o G_9(cg, packed se).  SE is the packed (-sg,+sg) constant.
__device__ __forceinline__ void applyFG(u64* P, float cb, float sb,
                                        const u64* DC, const u64* DS,
                                        u64 CG, u64 SE) {
    u64 CB = bc(cb), SB = bc(sb), NSB = bc(-sb);
#pragma unroll
    for (int a = 0; a < 2; a++) {
        u64 C  = f2fma(NSB, DS[a], f2mul(CB, DC[a]));
        u64 S  = f2fma(SB,  DC[a], f2mul(CB, DS[a]));
        u64 B  = f2mul(S, SE);                 // S*se
        u64 D  = f2mul(S, CG);                 // S*cg
        u64 E2 = f2mul(C, CG);                 // C*cg
        u64 F2 = f2mul(C, SE);                 // C*se
        u64 NS = f2neg(S);
        u64 x0 = P[4*a+0], x1 = P[4*a+1], x2 = P[4*a+2], x3 = P[4*a+3];
        P[4*a+0] = f2fma(C,         x0, f2fma(f2neg(B),  x1, f2mul(f2neg(D),  x3)));
        P[4*a+1] = f2fma(E2,        x1, f2fma(S,         x2, f2mul(f2neg(F2), x3)));
        P[4*a+2] = f2fma(NS,        x0, f2fma(f2neg(F2), x1, f2mul(f2neg(E2), x3)));
        P[4*a+3] = f2fma(f2neg(D),  x1, f2fma(C,         x2, f2mul(B,         x3)));
    }
}

// angle-vector spec tables
__device__ constexpr int aIdx[NIDX] = {1,2,3,4,5,6,7,8,9, 11,12,13,14,15,16,17,18,19, 0, 10, 9, 19};
__device__ constexpr int bIdx[NIDX] = {0,1,2,3,4,5,6,7,8, 10,11,12,13,14,15,16,17,18, -1,-1,-1,-1};

__global__ void __launch_bounds__(NTH, 1) rvqe_kernel(
    const int*   __restrict__ inputs,   // (64, 9, 6) int32
    const float* __restrict__ ua,       // (2, 10)
    const float* __restrict__ nth,      // (2, 10, 11)
    float*       __restrict__ out,
    int out_size)
{
    extern __shared__ u64 dyn[];
    u64* bufA = dyn + OFF_A;
    u64* bufB = dyn + OFF_B;
    u64* tab  = dyn + OFF_TAB;          // per-thread coef rows, stride CSW

    __shared__ u64   phi[32];           // compressed state (64 floats)
    __shared__ float uc[20], us[20];
    __shared__ u64   DC2[NIDX][2], DS2[NIDX][2];
    __shared__ float gc_sm[20], gs_sm[20];
    __shared__ u64   se9p[2];
    __shared__ float probs_sm[64];
    __shared__ int   tIdx[TT];

    const int t = threadIdx.x;
    const int b = blockIdx.x;
    const int* inb = inputs + b * TT * 6;

    // ---- precompute (phase 1: shared tables) ----
    if (t < 20) {
        float c, s; sincosf(0.5f * ua[t], &s, &c);
        uc[t] = c; us[t] = s;
        float cg, sg; sincosf(0.5f * nth[t * 11 + (t % 10)], &sg, &cg);
        gc_sm[t] = cg; gs_sm[t] = sg;
        if ((t % 10) == 9) se9p[t / 10] = pk(-sg, sg);
    }
    if (t < NIDX * 2) {
        int idx = t >> 1, a = t & 1;
        const float* A = nth + aIdx[idx] * 11;
        const float* Bp = (bIdx[idx] >= 0) ? (nth + bIdx[idx] * 11) : nullptr;
        float d8 = A[8] - (Bp ? Bp[8] : 0.f);
        float d9 = A[9] - (Bp ? Bp[9] : 0.f);
        float dlo = a ? d8 : 0.f;
        float dhi = dlo + d9;
        float cl, sl, ch, sh;
        sincosf(0.5f * dlo, &sl, &cl);
        sincosf(0.5f * dhi, &sh, &ch);
        DC2[idx][a] = pk(cl, ch);
        DS2[idx][a] = pk(sl, sh);
    }
    if (t < TT) {
        int idx = 0;
#pragma unroll
        for (int i = 0; i < 6; i++) idx |= (inb[t * 6 + i] & 1) << (5 - i);
        tIdx[t] = idx;
    }
    // init compressed state: phi = e0 (|0...0> on lanes 6..11), probs = 1
    if (t < 64) probs_sm[t] = 1.0f;
    if (t < 32) phi[t] = 0ULL;
    if (t == 0) phi[0] = pk(1.f, 0.f);
    __syncthreads();

    // ---- precompute (phase 2): T-coef table (idx<18); E/F base trig in regs ----
    float cbs4[4], sbs4[4];
    {
        u64* row = tab + t * CSW;
#pragma unroll
        for (int idx = 0; idx < NIDX; idx++) {
            const float* A = nth + aIdx[idx] * 11;
            const float* Bp = (bIdx[idx] >= 0) ? (nth + bIdx[idx] * 11) : nullptr;
            float base = A[10] - (Bp ? Bp[10] : 0.f);
#pragma unroll
            for (int i = 0; i < 8; i++)
                if ((t >> (7 - i)) & 1) base += A[i] - (Bp ? Bp[i] : 0.f);
            float c, s; sincosf(0.5f * base, &s, &c);
            if (idx < 18) {
                u64 CB = bc(c), SB = bc(s), NSB = bc(-s);
#pragma unroll
                for (int a = 0; a < 2; a++) {
                    u64 C = f2fma(NSB, DS2[idx][a], f2mul(CB, DC2[idx][a]));
                    u64 S = f2fma(SB,  DC2[idx][a], f2mul(CB, DS2[idx][a]));
                    row[idx * 4 + a * 2 + 0] = C;
                    row[idx * 4 + a * 2 + 1] = S;
                }
            } else {
                cbs4[idx - 18] = c; sbs4[idx - 18] = s;
            }
        }
    }
    __syncthreads();

    const u64* myCS = tab + t * CSW;
    u64 P[8];

    for (int step = 0; step < NSTEP; step++) {
        // ---- prologue: reconstruct from compressed phi ----
        {
            int j = tIdx[step];
            float prod = 1.0f / sqrtf(probs_sm[j]);
#pragma unroll
            for (int l = 0; l < 6; l++) {
                int x  = (t >> (7 - l)) & 1;
                int jl = (j >> (5 - l)) & 1;
                float f = (x == jl) ? uc[l] : (x ? us[l] : -us[l]);
                prod *= f;
            }
            u64 SIG = bc(prod);
            int pb = (t & 3) * 8;
#pragma unroll
            for (int jj = 0; jj < 8; jj++) P[jj] = f2mul(SIG, phi[pb + jj]);
        }

#pragma unroll
        for (int s = 0; s < 2; s++) {
            const float* ucc = uc + s * 10;
            const float* uss = us + s * 10;
            u64* bX = (s == 0) ? bufA : bufB;   // ping-pong roles per stage
            u64* bY = (s == 0) ? bufB : bufA;

            // stage RYs
            ry_lane8(P, ucc[8], uss[8]);
            {
                u64 C9 = bc(ucc[9]);
                u64 SW = pk(-uss[9], uss[9]);
                ry_lane9(P, C9, SW);
            }
            if (s == 0) {
                // lanes 0..5 absorbed into sigma; only lanes 6,7 remain
                ry_shfl(P, t, 2, ucc[6], uss[6]);
                ry_shfl(P, t, 1, ucc[7], uss[7]);
            } else {
#pragma unroll
                for (int l = 3; l <= 7; l++)
                    ry_shfl(P, t, 1 << (7 - l), ucc[l], uss[l]);
                ry_smem4(P, t, ucc[0], uss[0], ucc[1], uss[1], bY);
                ry_smem1(P, t, ucc[2], uss[2], bX);
            }

            // neuron chain: E C0 TG1 C1 TG2 ... TG9 C9 FG
            applyE(P, cbs4[s], sbs4[s], DC2[18 + s], DS2[18 + s]);
            ciy_smem(P, t, 128, (s == 0) ? bufA : bufB);      // C0
#pragma unroll
            for (int n = 1; n < 10; n++) {
                int gi = s * 10 + (n - 1);        // G gate being fused
                u64 CG = bc(gc_sm[gi]);
                u64 SG = bc(gs_sm[gi]);
                bool neg0, neg1;
                if (n - 1 <= 7) {
                    bool bit = (t >> (7 - (n - 1))) & 1;
                    neg0 = neg1 = !bit;           // se = bit ? +sg : -sg
                } else {                           // n-1 == 8: sign from a bit
                    neg0 = true; neg1 = false;
                }
                applyTG(P, myCS + (s * 9 + n - 1) * 4, CG, SG, neg0, neg1);
                if (n == 9)      ciy_lane9(P);
                else if (n == 8) ciy_lane8(P);
                else if (n >= 3) ciy_shfl(P, t, 1 << (7 - n));
                else if (n == 1) ciy_smem(P, t, 64, (s == 0) ? bufB : bufA);
                else             ciy_smem(P, t, 32, (s == 0) ? bufA : bufB);
            }
            applyFG(P, cbs4[2 + s], sbs4[2 + s], DC2[20 + s], DS2[20 + s],
                    bc(gc_sm[s * 10 + 9]), se9p[s]);
        }

        // ---- probs + compress ----
        u64 acc = 0ULL;
#pragma unroll
        for (int j = 0; j < 8; j++) acc = f2fma(P[j], P[j], acc);
        float alo, ahi; upk(acc, alo, ahi);
        float ssq = alo + ahi;
        ssq += __shfl_xor_sync(0xffffffffu, ssq, 1);
        ssq += __shfl_xor_sync(0xffffffffu, ssq, 2);
        if (!(t & 3)) {
            probs_sm[t >> 2] = ssq;
            out[(b * NSTEP + step) * 64 + (t >> 2)] = ssq;
        }
        if ((t >> 2) == tIdx[step + 1]) {
            int pb = (t & 3) * 8;
#pragma unroll
            for (int jj = 0; jj < 8; jj++) phi[pb + jj] = P[jj];
        }
        __syncthreads();
    }

    // ---- second tuple output: measured = inputs[:,1:] as float ----
    if (out_size > 32768 && t < 48) {
        out[32768 + b * 48 + t] = (float)inb[6 + t];
    }
}

} // namespace

extern "C" void kernel_launch(void* const* d_in, const int* in_sizes, int n_in,
                              void* d_out, int out_size) {
    const int*   inputs = nullptr;
    const float* ua     = nullptr;
    const float* nth    = nullptr;
    for (int i = 0; i < n_in; i++) {
        if (in_sizes[i] == 3456)      inputs = (const int*)d_in[i];
        else if (in_sizes[i] == 20)   ua     = (const float*)d_in[i];
        else if (in_sizes[i] == 220)  nth    = (const float*)d_in[i];
    }
    const int dyn_bytes = DYN_U64 * 8;   // 186368
    cudaFuncSetAttribute(rvqe_kernel, cudaFuncAttributeMaxDynamicSharedMemorySize,
                         dyn_bytes);
    rvqe_kernel<<<64, NTH, dyn_bytes>>>(inputs, ua, nth, (float*)d_out, out_size);
}

// round 17
// speedup vs baseline: 1.0457x; 1.0457x over previous
#include <cuda_runtime.h>
#include <math.h>
#include <stdint.h>

// RVQE: 12-qubit real statevector recurrent cell, B=64, T=9 (8 scan steps).
// One CTA per batch element; state = 4096 floats = 256 threads x 8 packed f32x2.
// Global amplitude index g12 (12 bits), g12 = (t << 4) | r:
//   r bits: bit0=lane11(anc1), bit1=lane10(anc0), bit2=lane9(PACKED), bit3=lane8
//   t bits 0..4 (warp lane): lanes 7,6,5,4,3  -> __shfl_xor (mask 1<<(7-lane))
//   t bits 5,6,7: lanes 2,1,0 -> smem exchange
// PACKING: P[j], j = a*4 + i, i = (anc0<<1)|anc1, a = lane8 bit.
//   P[j].lo = lane9=0, P[j].hi = lane9=1.
//
// Fused neuron algebra (validated rounds 3/5/8): per stage
//   chain = E(a_0) C_0 G_0 T'(D1) C_1 G_1 ... T'(D9) C_9 G_9 F(a_9)
// SPARSITY EXPLOIT (validated round 14): steps start from compressed phi;
// P = sigma_t * invn * phi[chunk] replaces stage-0 lane0..5 RYs + projection.
// Step-invariant T' coefficient table in smem (round 15).
// NEW (this round): stage-1's two smem RY exchanges (4-way lanes 0,1 + 2-way
// lane 2) fused into ONE 8-way gather over t bits 7,6,5 — one exchange
// round-trip saved per step. 7 exchanges/step, ping-pong A/B.

namespace {

typedef unsigned long long u64;

constexpr int NTH   = 256;
constexpr int TT    = 9;
constexpr int NSTEP = 8;
constexpr int NIDX  = 22;   // 18 deltas + 2 entries + 2 trailings
constexpr int STq   = 9;    // exch stride in u64 (8 + 1 pad; odd -> conflict-free)
constexpr int CSW   = 73;   // coef table per-thread stride in u64 (72 + 1 pad)
constexpr u64 SGN2  = 0x8000000080000000ULL;

// dynamic smem layout (u64 units)
constexpr int OFF_A   = 0;
constexpr int OFF_B   = NTH * STq;         // 2304
constexpr int OFF_TAB = OFF_B + NTH * STq; // 4608
constexpr int DYN_U64 = OFF_TAB + NTH * CSW; // 23296 u64 = 186368 B

__device__ __forceinline__ u64 pk(float lo, float hi) {
    u64 r; asm("mov.b64 %0,{%1,%2};" : "=l"(r) : "f"(lo), "f"(hi)); return r;
}
__device__ __forceinline__ void upk(u64 u, float& lo, float& hi) {
    asm("mov.b64 {%0,%1},%2;" : "=f"(lo), "=f"(hi) : "l"(u));
}
__device__ __forceinline__ u64 bc(float x) { return pk(x, x); }
__device__ __forceinline__ u64 f2mul(u64 a, u64 b) {
    u64 d; asm("mul.rn.f32x2 %0,%1,%2;" : "=l"(d) : "l"(a), "l"(b)); return d;
}
__device__ __forceinline__ u64 f2fma(u64 a, u64 b, u64 c) {
    u64 d; asm("fma.rn.f32x2 %0,%1,%2,%3;" : "=l"(d) : "l"(a), "l"(b), "l"(c)); return d;
}
__device__ __forceinline__ u64 f2neg(u64 a) { return a ^ SGN2; }
__device__ __forceinline__ u64 f2swap(u64 a) { float lo, hi; upk(a, lo, hi); return pk(hi, lo); }

// ---- stage RY pieces ----

__device__ __forceinline__ void ry_lane9(u64* P, u64 C, u64 SW) {
#pragma unroll
    for (int j = 0; j < 8; j++)
        P[j] = f2fma(SW, f2swap(P[j]), f2mul(C, P[j]));
}

__device__ __forceinline__ void ry_lane8(u64* P, float c, float s) {
    u64 C = bc(c), S = bc(s), NS = bc(-s);
#pragma unroll
    for (int i = 0; i < 4; i++) {
        u64 u = P[i], w = P[4 + i];
        P[i]     = f2fma(NS, w, f2mul(C, u));
        P[4 + i] = f2fma(S,  u, f2mul(C, w));
    }
}

__device__ __forceinline__ void ry_shfl(u64* P, int t, int m, float c, float s) {
    u64 C = bc(c), SE = bc((t & m) ? s : -s);
#pragma unroll
    for (int j = 0; j < 8; j++) {
        u64 w = __shfl_xor_sync(0xffffffffu, P[j], m);
        P[j] = f2fma(SE, w, f2mul(C, P[j]));
    }
}

// Fused RY(lane0)*RY(lane1)*RY(lane2) on t bits 7,6,5: ONE sync, 8-way gather.
__device__ __forceinline__ void ry_smem8(u64* P, int t,
                                         float c0, float s0, float c1, float s1,
                                         float c2, float s2, u64* X) {
#pragma unroll
    for (int j = 0; j < 8; j++) X[t * STq + j] = P[j];
    __syncthreads();
    float F0 = (t & 128) ? s0 : -s0;
    float F1 = (t &  64) ? s1 : -s1;
    float F2 = (t &  32) ? s2 : -s2;
    u64 k[8];
    const u64* rows[8];
#pragma unroll
    for (int d = 0; d < 8; d++) {
        float kk = (d & 4) ? F0 : c0;
        kk *= (d & 2) ? F1 : c1;
        kk *= (d & 1) ? F2 : c2;
        k[d] = bc(kk);
        int m = ((d & 4) ? 128 : 0) | ((d & 2) ? 64 : 0) | ((d & 1) ? 32 : 0);
        rows[d] = X + (t ^ m) * STq;
    }
#pragma unroll
    for (int j = 0; j < 8; j++) {
        u64 acc = f2mul(k[0], rows[0][j]);
#pragma unroll
        for (int d = 1; d < 8; d++) acc = f2fma(k[d], rows[d][j], acc);
        P[j] = acc;
    }
    // no trailing sync: ping-pong ordering
}

// ---- CiY pieces (ctrl anc1: odd j) ----

__device__ __forceinline__ void ciy_lane9(u64* P) {
#pragma unroll
    for (int j = 1; j < 8; j += 2) {
        float lo, hi; upk(P[j], lo, hi);
        P[j] = pk(hi, -lo);
    }
}

__device__ __forceinline__ void ciy_lane8(u64* P) {
#pragma unroll
    for (int i = 1; i < 4; i += 2) {
        u64 p0 = P[i];
        P[i] = P[4 + i];
        P[4 + i] = f2neg(p0);
    }
}

__device__ __forceinline__ void ciy_shfl(u64* P, int t, int m) {
    u64 sgn = (t & m) ? SGN2 : 0ULL;
#pragma unroll
    for (int j = 1; j < 8; j += 2) {
        u64 w = __shfl_xor_sync(0xffffffffu, P[j], m);
        P[j] = w ^ sgn;
    }
}

// Cross-warp CiY: one sync, ping-pong buffer.
__device__ __forceinline__ void ciy_smem(u64* P, int t, int m, u64* X) {
#pragma unroll
    for (int j = 1; j < 8; j += 2) X[t * STq + (j >> 1)] = P[j];
    __syncthreads();
    const u64* p = X + (t ^ m) * STq;
    u64 sgn = (t & m) ? SGN2 : 0ULL;
#pragma unroll
    for (int j = 1; j < 8; j += 2) P[j] = p[j >> 1] ^ sgn;
    // no trailing sync: ping-pong ordering
}

// ---- fused neuron ops (packed over lane9; loop over a = lane8 bit) ----
// x_i = P[a*4+i]: x0=(0,0) x1=(0,1) x2=(1,0) x3=(1,1) of (anc0,anc1)

// T' with precomputed coefficients: cs = {C0,S0,C1,S1} in the per-thread table.
__device__ __forceinline__ void applyT_tab(u64* P, const u64* cs) {
#pragma unroll
    for (int a = 0; a < 2; a++) {
        u64 C  = cs[a * 2 + 0];
        u64 S  = cs[a * 2 + 1];
        u64 NS = f2neg(S);
        u64 x0 = P[4*a+0], x1 = P[4*a+1], x2 = P[4*a+2], x3 = P[4*a+3];
        P[4*a+0] = f2fma(S,  x3, f2mul(C, x0));
        P[4*a+1] = f2fma(NS, x2, f2mul(C, x1));
        P[4*a+2] = f2fma(S,  x1, f2mul(C, x2));
        P[4*a+3] = f2fma(NS, x0, f2mul(C, x3));
    }
}

__device__ __forceinline__ void applyE(u64* P, float cb, float sb,
                                       const u64* DC, const u64* DS) {
    u64 CB = bc(cb), SB = bc(sb), NSB = bc(-sb);
#pragma unroll
    for (int a = 0; a < 2; a++) {
        u64 C  = f2fma(NSB, DS[a], f2mul(CB, DC[a]));
        u64 S  = f2fma(SB,  DC[a], f2mul(CB, DS[a]));
        u64 NS = f2neg(S);
        u64 x0 = P[4*a+0], x1 = P[4*a+1], x2 = P[4*a+2], x3 = P[4*a+3];
        P[4*a+0] = f2fma(NS, x2, f2mul(C, x0));
        P[4*a+1] = f2fma(NS, x3, f2mul(C, x1));
        P[4*a+2] = f2fma(S,  x1, f2mul(C, x3));
        P[4*a+3] = f2neg(f2fma(S, x0, f2mul(C, x2)));
    }
}

__device__ __forceinline__ void applyF(u64* P, float cb, float sb,
                                       const u64* DC, const u64* DS) {
    u64 CB = bc(cb), SB = bc(sb), NSB = bc(-sb);
#pragma unroll
    for (int a = 0; a < 2; a++) {
        u64 C  = f2fma(NSB, DS[a], f2mul(CB, DC[a]));
        u64 S  = f2fma(SB,  DC[a], f2mul(CB, DS[a]));
        u64 NS = f2neg(S);
        u64 x0 = P[4*a+0], x1 = P[4*a+1], x2 = P[4*a+2], x3 = P[4*a+3];
        P[4*a+0] = f2fma(NS, x3, f2mul(C, x0));
        P[4*a+1] = f2fma(S,  x2, f2mul(C, x1));
        P[4*a+2] = f2neg(f2fma(S, x0, f2mul(C, x3)));
        P[4*a+3] = f2fma(NS, x1, f2mul(C, x2));
    }
}

__device__ __forceinline__ void applyG_se(u64* P, u64 C, u64 SE0, u64 SE1) {
    u64 NSE0 = f2neg(SE0), NSE1 = f2neg(SE1);
    {
        u64 x1 = P[1], x3 = P[3];
        P[1] = f2fma(NSE0, x3, f2mul(C, x1));
        P[3] = f2fma(SE0,  x1, f2mul(C, x3));
    }
    {
        u64 x1 = P[5], x3 = P[7];
        P[5] = f2fma(NSE1, x3, f2mul(C, x1));
        P[7] = f2fma(SE1,  x1, f2mul(C, x3));
    }
}

// angle-vector spec tables
__device__ constexpr int aIdx[NIDX] = {1,2,3,4,5,6,7,8,9, 11,12,13,14,15,16,17,18,19, 0, 10, 9, 19};
__device__ constexpr int bIdx[NIDX] = {0,1,2,3,4,5,6,7,8, 10,11,12,13,14,15,16,17,18, -1,-1,-1,-1};

__global__ void __launch_bounds__(NTH, 1) rvqe_kernel(
    const int*   __restrict__ inputs,   // (64, 9, 6) int32
    const float* __restrict__ ua,       // (2, 10)
    const float* __restrict__ nth,      // (2, 10, 11)
    float*       __restrict__ out,
    int out_size)
{
    extern __shared__ u64 dyn[];
    u64* bufA = dyn + OFF_A;
    u64* bufB = dyn + OFF_B;
    u64* tab  = dyn + OFF_TAB;          // per-thread coef rows, stride CSW

    __shared__ u64   phi[32];           // compressed state (64 floats)
    __shared__ float uc[20], us[20];
    __shared__ u64   DC2[NIDX][2], DS2[NIDX][2];
    __shared__ float gc_sm[20], gs_sm[20];
    __shared__ u64   se9p[2];
    __shared__ float probs_sm[64];
    __shared__ int   tIdx[TT];

    const int t = threadIdx.x;
    const int b = blockIdx.x;
    const int* inb = inputs + b * TT * 6;

    // ---- precompute (phase 1: shared tables) ----
    if (t < 20) {
        float c, s; sincosf(0.5f * ua[t], &s, &c);
        uc[t] = c; us[t] = s;
        float cg, sg; sincosf(0.5f * nth[t * 11 + (t % 10)], &sg, &cg);
        gc_sm[t] = cg; gs_sm[t] = sg;
        if ((t % 10) == 9) se9p[t / 10] = pk(-sg, sg);
    }
    if (t < NIDX * 2) {
        int idx = t >> 1, a = t & 1;
        const float* A = nth + aIdx[idx] * 11;
        const float* Bp = (bIdx[idx] >= 0) ? (nth + bIdx[idx] * 11) : nullptr;
        float d8 = A[8] - (Bp ? Bp[8] : 0.f);
        float d9 = A[9] - (Bp ? Bp[9] : 0.f);
        float dlo = a ? d8 : 0.f;
        float dhi = dlo + d9;
        float cl, sl, ch, sh;
        sincosf(0.5f * dlo, &sl, &cl);
        sincosf(0.5f * dhi, &sh, &ch);
        DC2[idx][a] = pk(cl, ch);
        DS2[idx][a] = pk(sl, sh);
    }
    if (t < TT) {
        int idx = 0;
#pragma unroll
        for (int i = 0; i < 6; i++) idx |= (inb[t * 6 + i] & 1) << (5 - i);
        tIdx[t] = idx;
    }
    // init compressed state: phi = e0 (|0...0> on lanes 6..11), probs = 1
    if (t < 64) probs_sm[t] = 1.0f;
    if (t < 32) phi[t] = 0ULL;
    if (t == 0) phi[0] = pk(1.f, 0.f);
    __syncthreads();

    // ---- precompute (phase 2): T-coef table (idx<18); E/F base trig in regs ----
    float cbs4[4], sbs4[4];
    {
        u64* row = tab + t * CSW;
#pragma unroll
        for (int idx = 0; idx < NIDX; idx++) {
            const float* A = nth + aIdx[idx] * 11;
            const float* Bp = (bIdx[idx] >= 0) ? (nth + bIdx[idx] * 11) : nullptr;
            float base = A[10] - (Bp ? Bp[10] : 0.f);
#pragma unroll
            for (int i = 0; i < 8; i++)
                if ((t >> (7 - i)) & 1) base += A[i] - (Bp ? Bp[i] : 0.f);
            float c, s; sincosf(0.5f * base, &s, &c);
            if (idx < 18) {
                u64 CB = bc(c), SB = bc(s), NSB = bc(-s);
#pragma unroll
                for (int a = 0; a < 2; a++) {
                    u64 C = f2fma(NSB, DS2[idx][a], f2mul(CB, DC2[idx][a]));
                    u64 S = f2fma(SB,  DC2[idx][a], f2mul(CB, DS2[idx][a]));
                    row[idx * 4 + a * 2 + 0] = C;
                    row[idx * 4 + a * 2 + 1] = S;
                }
            } else {
                cbs4[idx - 18] = c; sbs4[idx - 18] = s;
            }
        }
    }
    __syncthreads();

    const u64* myCS = tab + t * CSW;
    u64 P[8];

    for (int step = 0; step < NSTEP; step++) {
        // ---- prologue: reconstruct from compressed phi ----
        {
            int j = tIdx[step];
            float prod = 1.0f / sqrtf(probs_sm[j]);
#pragma unroll
            for (int l = 0; l < 6; l++) {
                int x  = (t >> (7 - l)) & 1;
                int jl = (j >> (5 - l)) & 1;
                float f = (x == jl) ? uc[l] : (x ? us[l] : -us[l]);
                prod *= f;
            }
            u64 SIG = bc(prod);
            int pb = (t & 3) * 8;
#pragma unroll
            for (int jj = 0; jj < 8; jj++) P[jj] = f2mul(SIG, phi[pb + jj]);
        }

        // ======== stage 0 ========
        // exchanges this stage: ciy0(bufA), ciy1(bufB), ciy2(bufA)
        {
            const float* ucc = uc;
            const float* uss = us;
            ry_lane8(P, ucc[8], uss[8]);
            {
                u64 C9 = bc(ucc[9]);
                u64 SW = pk(-uss[9], uss[9]);
                ry_lane9(P, C9, SW);
            }
            ry_shfl(P, t, 2, ucc[6], uss[6]);
            ry_shfl(P, t, 1, ucc[7], uss[7]);

            applyE(P, cbs4[0], sbs4[0], DC2[18], DS2[18]);
            ciy_smem(P, t, 128, bufA);                 // C0
            {
                float sg = ((t >> 7) & 1) ? gs_sm[0] : -gs_sm[0];
                u64 SE = bc(sg);
                applyG_se(P, bc(gc_sm[0]), SE, SE);
            }
#pragma unroll
            for (int n = 1; n < 10; n++) {
                applyT_tab(P, myCS + (n - 1) * 4);
                if (n == 9)      ciy_lane9(P);
                else if (n == 8) ciy_lane8(P);
                else if (n >= 3) ciy_shfl(P, t, 1 << (7 - n));
                else if (n == 1) ciy_smem(P, t, 64, bufB);
                else             ciy_smem(P, t, 32, bufA);
                u64 C = bc(gc_sm[n]);
                if (n <= 7) {
                    float sg = ((t >> (7 - n)) & 1) ? gs_sm[n] : -gs_sm[n];
                    u64 SE = bc(sg);
                    applyG_se(P, C, SE, SE);
                } else if (n == 8) {
                    u64 SE1 = bc(gs_sm[n]);
                    applyG_se(P, C, f2neg(SE1), SE1);
                } else {
                    applyG_se(P, C, se9p[0], se9p[0]);
                }
            }
            applyF(P, cbs4[2], sbs4[2], DC2[20], DS2[20]);
        }

        // ======== stage 1 (full) ========
        // exchanges this stage: ry8(bufB), ciy0(bufA), ciy1(bufB), ciy2(bufA)
        {
            const float* ucc = uc + 10;
            const float* uss = us + 10;
            ry_lane8(P, ucc[8], uss[8]);
            {
                u64 C9 = bc(ucc[9]);
                u64 SW = pk(-uss[9], uss[9]);
                ry_lane9(P, C9, SW);
            }
#pragma unroll
            for (int l = 3; l <= 7; l++)
                ry_shfl(P, t, 1 << (7 - l), ucc[l], uss[l]);
            ry_smem8(P, t, ucc[0], uss[0], ucc[1], uss[1], ucc[2], uss[2], bufB);

            applyE(P, cbs4[1], sbs4[1], DC2[19], DS2[19]);
            ciy_smem(P, t, 128, bufA);                 // C0
            {
                float sg = ((t >> 7) & 1) ? gs_sm[10] : -gs_sm[10];
                u64 SE = bc(sg);
                applyG_se(P, bc(gc_sm[10]), SE, SE);
            }
#pragma unroll
            for (int n = 1; n < 10; n++) {
                applyT_tab(P, myCS + (9 + n - 1) * 4);
                if (n == 9)      ciy_lane9(P);
                else if (n == 8) ciy_lane8(P);
                else if (n >= 3) ciy_shfl(P, t, 1 << (7 - n));
                else if (n == 1) ciy_smem(P, t, 64, bufB);
                else             ciy_smem(P, t, 32, bufA);
                int gi = 10 + n;
                u64 C = bc(gc_sm[gi]);
                if (n <= 7) {
                    float sg = ((t >> (7 - n)) & 1) ? gs_sm[gi] : -gs_sm[gi];
                    u64 SE = bc(sg);
                    applyG_se(P, C, SE, SE);
                } else if (n == 8) {
                    u64 SE1 = bc(gs_sm[gi]);
                    applyG_se(P, C, f2neg(SE1), SE1);
                } else {
                    applyG_se(P, C, se9p[1], se9p[1]);
                }
            }
            applyF(P, cbs4[3], sbs4[3], DC2[21], DS2[21]);
        }

        // ---- probs + compress ----
        u64 acc = 0ULL;
#pragma unroll
        for (int j = 0; j < 8; j++) acc = f2fma(P[j], P[j], acc);
        float alo, ahi; upk(acc, alo, ahi);
        float ssq = alo + ahi;
        ssq += __shfl_xor_sync(0xffffffffu, ssq, 1);
        ssq += __shfl_xor_sync(0xffffffffu, ssq, 2);
        if (!(t & 3)) {
            probs_sm[t >> 2] = ssq;
            out[(b * NSTEP + step) * 64 + (t >> 2)] = ssq;
        }
        if ((t >> 2) == tIdx[step + 1]) {
            int pb = (t & 3) * 8;
#pragma unroll
            for (int jj = 0; jj < 8; jj++) phi[pb + jj] = P[jj];
        }
        __syncthreads();
    }

    // ---- second tuple output: measured = inputs[:,1:] as float ----
    if (out_size > 32768 && t < 48) {
        out[32768 + b * 48 + t] = (float)inb[6 + t];
    }
}

} // namespace

extern "C" void kernel_launch(void* const* d_in, const int* in_sizes, int n_in,
                              void* d_out, int out_size) {
    const int*   inputs = nullptr;
    const float* ua     = nullptr;
    const float* nth    = nullptr;
    for (int i = 0; i < n_in; i++) {
        if (in_sizes[i] == 3456)      inputs = (const int*)d_in[i];
        else if (in_sizes[i] == 20)   ua     = (const float*)d_in[i];
        else if (in_sizes[i] == 220)  nth    = (const float*)d_in[i];
    }
    const int dyn_bytes = DYN_U64 * 8;   // 186368
    cudaFuncSetAttribute(rvqe_kernel, cudaFuncAttributeMaxDynamicSharedMemorySize,
                         dyn_bytes);
    rvqe_kernel<<<64, NTH, dyn_bytes>>>(inputs, ua, nth, (float*)d_out, out_size);
}